// round 1
// baseline (speedup 1.0000x reference)
#include <cuda_runtime.h>
#include <math.h>

#define B_  16
#define C_  512
#define HW  1024
#define NH  8
#define DH  64

// Scratch (device globals — no allocation allowed)
__device__ float g_h[(size_t)B_ * C_ * HW];          // GroupNorm output  (B, C, HW)
__device__ float g_qkv[(size_t)B_ * 3 * C_ * HW];    // qkv conv output   (B, 3C, HW)
__device__ float g_attn[(size_t)B_ * C_ * HW];       // attention output, already permuted to (B, C, HW)

// ---------------------------------------------------------------------------
// GroupNorm: 32 groups of 16 channels; one block per (b, group)
// ---------------------------------------------------------------------------
__global__ __launch_bounds__(256) void gn_kernel(const float* __restrict__ x,
                                                 const float* __restrict__ gamma,
                                                 const float* __restrict__ beta) {
    int bg = blockIdx.x;           // 0..511
    int b = bg >> 5, g = bg & 31;
    const float* xp = x   + ((size_t)b * C_ + g * 16) * HW;
    float*       hp = g_h + ((size_t)b * C_ + g * 16) * HW;

    float s = 0.f, s2 = 0.f;
    for (int i = threadIdx.x; i < 16 * HW; i += 256) {
        float v = xp[i];
        s += v; s2 += v * v;
    }
    __shared__ float rs[256], rs2[256];
    rs[threadIdx.x] = s; rs2[threadIdx.x] = s2;
    __syncthreads();
    for (int o = 128; o > 0; o >>= 1) {
        if (threadIdx.x < o) {
            rs[threadIdx.x]  += rs[threadIdx.x + o];
            rs2[threadIdx.x] += rs2[threadIdx.x + o];
        }
        __syncthreads();
    }
    float mean = rs[0] * (1.f / 16384.f);
    float var  = rs2[0] * (1.f / 16384.f) - mean * mean;
    float inv  = rsqrtf(var + 1e-5f);

    for (int i = threadIdx.x; i < 16 * HW; i += 256) {
        int c = g * 16 + (i >> 10);
        hp[i] = (xp[i] - mean) * inv * gamma[c] + beta[c];
    }
}

// ---------------------------------------------------------------------------
// Batched SGEMM:  C[b][m][n] = sum_k A[m][k] * Bmat[b][k][n] + bias[m] (+ R[b][m][n])
// mode 0: Bmat = g_h,    Cout = g_qkv, no residual      (qkv projection)
// mode 1: Bmat = g_attn, Cout = param, residual = x     (output projection)
// Tile 128x128, BK=8, 256 threads, 8x8 micro-tile (split 4+4 to avoid bank conflicts)
// ---------------------------------------------------------------------------
__global__ __launch_bounds__(256) void sgemm_kernel(const float* __restrict__ A,
                                                    const float* __restrict__ bias,
                                                    const float* __restrict__ Rm,
                                                    float* __restrict__ Cparam,
                                                    int M, int N, int K, int mode) {
    const float* Bbase = (mode == 0) ? g_h : g_attn;
    float*       Cbase = (mode == 0) ? g_qkv : Cparam;

    int bz = blockIdx.z;
    const float* Bm = Bbase + (size_t)bz * K * N;
    float*       Cm = Cbase + (size_t)bz * M * N;
    const float* Rb = Rm ? (Rm + (size_t)bz * M * N) : nullptr;

    int m0 = blockIdx.y * 128;
    int n0 = blockIdx.x * 128;

    __shared__ float As[8][128];
    __shared__ float Bs[8][128];

    int tid  = threadIdx.x;
    int arow = tid >> 1;            // 0..127
    int acol = (tid & 1) * 4;       // 0 or 4
    int brow = tid >> 5;            // 0..7
    int bcol = (tid & 31) * 4;      // 0..124

    int ty = tid >> 4;              // 0..15
    int tx = tid & 15;              // 0..15

    float acc[8][8];
    #pragma unroll
    for (int i = 0; i < 8; i++)
        #pragma unroll
        for (int j = 0; j < 8; j++) acc[i][j] = 0.f;

    for (int k0 = 0; k0 < K; k0 += 8) {
        float4 av = *(const float4*)&A [(size_t)(m0 + arow) * K + k0 + acol];
        float4 bv = *(const float4*)&Bm[(size_t)(k0 + brow) * N + n0 + bcol];
        __syncthreads();
        As[acol + 0][arow] = av.x;
        As[acol + 1][arow] = av.y;
        As[acol + 2][arow] = av.z;
        As[acol + 3][arow] = av.w;
        *(float4*)&Bs[brow][bcol] = bv;
        __syncthreads();

        #pragma unroll
        for (int k = 0; k < 8; k++) {
            float a[8], b[8];
            *(float4*)&a[0] = *(const float4*)&As[k][ty * 4];
            *(float4*)&a[4] = *(const float4*)&As[k][64 + ty * 4];
            *(float4*)&b[0] = *(const float4*)&Bs[k][tx * 4];
            *(float4*)&b[4] = *(const float4*)&Bs[k][64 + tx * 4];
            #pragma unroll
            for (int i = 0; i < 8; i++)
                #pragma unroll
                for (int j = 0; j < 8; j++)
                    acc[i][j] = fmaf(a[i], b[j], acc[i][j]);
        }
    }

    // Epilogue
    #pragma unroll
    for (int i = 0; i < 8; i++) {
        int m = m0 + ((i < 4) ? (ty * 4 + i) : (64 + ty * 4 + i - 4));
        float bi = bias[m];
        #pragma unroll
        for (int jh = 0; jh < 2; jh++) {
            int n = n0 + jh * 64 + tx * 4;
            float4 o;
            o.x = acc[i][jh * 4 + 0] + bi;
            o.y = acc[i][jh * 4 + 1] + bi;
            o.z = acc[i][jh * 4 + 2] + bi;
            o.w = acc[i][jh * 4 + 3] + bi;
            if (Rb) {
                float4 r = *(const float4*)&Rb[(size_t)m * N + n];
                o.x += r.x; o.y += r.y; o.z += r.z; o.w += r.w;
            }
            *(float4*)&Cm[(size_t)m * N + n] = o;
        }
    }
}

// ---------------------------------------------------------------------------
// Attention: one thread per query row, K/V tiles (64 keys) staged in SMEM.
// Scores are bounded (|s| < ~3), so exact softmax without max subtraction.
// Writes output with the reference's head-major rearrange applied:
//   bh = b*8 + head  ->  out batch = bh % 16, channel block = (bh / 16)*64
// ---------------------------------------------------------------------------
__global__ __launch_bounds__(128) void attn_kernel() {
    const float SCALE = 0.044194173824159216f;   // 512^(-0.5)
    int bh   = blockIdx.y;          // 0..127
    int b    = bh >> 3;
    int head = bh & 7;
    int i    = blockIdx.x * 128 + threadIdx.x;   // query row 0..1023

    const float* base = g_qkv + (size_t)b * 3 * C_ * HW + (size_t)head * 192 * HW;
    const float* Qp = base;                 // [64][1024]
    const float* Kp = base + (size_t)64  * HW;
    const float* Vp = base + (size_t)128 * HW;

    float q[64];
    #pragma unroll
    for (int c = 0; c < 64; c++) q[c] = Qp[(size_t)c * HW + i] * SCALE;

    float acc[64];
    #pragma unroll
    for (int c = 0; c < 64; c++) acc[c] = 0.f;
    float l = 0.f;

    __shared__ float Ks[64][64];   // [channel][key]
    __shared__ float Vs[64][64];

    for (int j0 = 0; j0 < HW; j0 += 64) {
        __syncthreads();
        for (int t = threadIdx.x; t < 64 * 16; t += 128) {
            int c = t >> 4, j4 = (t & 15) << 2;
            *(float4*)&Ks[c][j4] = *(const float4*)&Kp[(size_t)c * HW + j0 + j4];
            *(float4*)&Vs[c][j4] = *(const float4*)&Vp[(size_t)c * HW + j0 + j4];
        }
        __syncthreads();

        for (int j = 0; j < 64; j++) {
            float s = 0.f;
            #pragma unroll
            for (int c = 0; c < 64; c++) s = fmaf(q[c], Ks[c][j], s);
            float p = __expf(fminf(s, 30.f));
            l += p;
            #pragma unroll
            for (int c = 0; c < 64; c++) acc[c] = fmaf(p, Vs[c][j], acc[c]);
        }
    }

    float invl = 1.f / l;
    int ob = bh & 15;          // output batch
    int oh = bh >> 4;          // output channel block
    float* out = g_attn + ((size_t)ob * C_ + (size_t)oh * 64) * HW + i;
    #pragma unroll
    for (int c = 0; c < 64; c++) out[(size_t)c * HW] = acc[c] * invl;
}

// ---------------------------------------------------------------------------
extern "C" void kernel_launch(void* const* d_in, const int* in_sizes, int n_in,
                              void* d_out, int out_size) {
    const float* x      = (const float*)d_in[0];
    const float* gamma  = (const float*)d_in[1];
    const float* beta   = (const float*)d_in[2];
    const float* w_qkv  = (const float*)d_in[3];
    const float* b_qkv  = (const float*)d_in[4];
    const float* w_proj = (const float*)d_in[5];
    const float* b_proj = (const float*)d_in[6];
    float* out = (float*)d_out;

    // 1) GroupNorm
    gn_kernel<<<B_ * 32, 256>>>(x, gamma, beta);

    // 2) QKV projection: M=1536, N=1024, K=512 per batch
    {
        dim3 grid(HW / 128, (3 * C_) / 128, B_);
        sgemm_kernel<<<grid, 256>>>(w_qkv, b_qkv, nullptr, nullptr,
                                    3 * C_, HW, C_, 0);
    }

    // 3) Attention (128 bh, 8 row-blocks of 128)
    {
        dim3 grid(HW / 128, B_ * NH);
        attn_kernel<<<grid, 128>>>();
    }

    // 4) Output projection + residual: M=512, N=1024, K=512 per batch
    {
        dim3 grid(HW / 128, C_ / 128, B_);
        sgemm_kernel<<<grid, 256>>>(w_proj, b_proj, x, out,
                                    C_, HW, C_, 1);
    }
}

// round 4
// speedup vs baseline: 8.9432x; 8.9432x over previous
#include <cuda_runtime.h>
#include <cuda_bf16.h>
#include <cstdint>

#define B_  16
#define C_  512
#define HW  1024
#define SCALE_F 0.044194173824159216f   // 512^-0.5

// ---------------- scratch (device globals) ----------------
__device__ __nv_bfloat16 g_hT  [(size_t)B_ * HW * C_];      // [b][pos][ch]
__device__ __nv_bfloat16 g_qkvT[(size_t)B_ * HW * 3 * C_];  // [b][pos][och], q pre-scaled
__device__ __nv_bfloat16 g_attnT[(size_t)B_ * HW * C_];     // [b][pos][ch] (head-major permuted)
__device__ __nv_bfloat16 g_wqkv[(size_t)3 * C_ * C_];       // [och][ch]
__device__ __nv_bfloat16 g_wproj[(size_t)C_ * C_];          // [och][ch]

// ---------------- helpers ----------------
__device__ __forceinline__ uint32_t smem_u32(const void* p) {
    uint32_t a;
    asm("{ .reg .u64 t; cvta.to.shared.u64 t, %1; cvt.u32.u64 %0, t; }" : "=r"(a) : "l"(p));
    return a;
}
#define CP16(dst, src) asm volatile("cp.async.cg.shared.global [%0], [%1], 16;" :: "r"(dst), "l"(src))
#define CP_COMMIT()    asm volatile("cp.async.commit_group;" ::: "memory")
#define CP_WAIT(n)     asm volatile("cp.async.wait_group %0;" :: "n"(n) : "memory")

__device__ __forceinline__ void ldm_x4(uint32_t* r, uint32_t a) {
    asm volatile("ldmatrix.sync.aligned.m8n8.x4.shared.b16 {%0,%1,%2,%3}, [%4];"
        : "=r"(r[0]), "=r"(r[1]), "=r"(r[2]), "=r"(r[3]) : "r"(a));
}
__device__ __forceinline__ void ldm_x4t(uint32_t* r, uint32_t a) {
    asm volatile("ldmatrix.sync.aligned.m8n8.x4.trans.shared.b16 {%0,%1,%2,%3}, [%4];"
        : "=r"(r[0]), "=r"(r[1]), "=r"(r[2]), "=r"(r[3]) : "r"(a));
}
__device__ __forceinline__ void mma_bf16(float* d, const uint32_t* a, uint32_t b0, uint32_t b1) {
    asm volatile("mma.sync.aligned.m16n8k16.row.col.f32.bf16.bf16.f32 "
        "{%0,%1,%2,%3}, {%4,%5,%6,%7}, {%8,%9}, {%0,%1,%2,%3};"
        : "+f"(d[0]), "+f"(d[1]), "+f"(d[2]), "+f"(d[3])
        : "r"(a[0]), "r"(a[1]), "r"(a[2]), "r"(a[3]), "r"(b0), "r"(b1));
}
__device__ __forceinline__ uint32_t pack_bf2(float lo, float hi) {
    __nv_bfloat162 t = __floats2bfloat162_rn(lo, hi);
    return *(uint32_t*)&t;
}

// ---------------- weight convert ----------------
__global__ __launch_bounds__(256) void conv_kernel(const float* __restrict__ wq,
                                                   const float* __restrict__ wp) {
    int i = blockIdx.x * 256 + threadIdx.x;
    if (i < 3 * C_ * C_) g_wqkv[i]  = __float2bfloat16_rn(wq[i]);
    if (i < C_ * C_)     g_wproj[i] = __float2bfloat16_rn(wp[i]);
}

// ---------------- GroupNorm -> transposed bf16 ----------------
__global__ __launch_bounds__(256) void gn_kernel(const float* __restrict__ x,
                                                 const float* __restrict__ gamma,
                                                 const float* __restrict__ beta) {
    int b = blockIdx.x >> 5, g = blockIdx.x & 31;
    const float* xp = x + ((size_t)b * C_ + g * 16) * HW;
    float s = 0.f, s2 = 0.f;
    for (int i = threadIdx.x; i < 16 * HW; i += 256) { float v = xp[i]; s += v; s2 += v * v; }
    __shared__ float rs[256], rs2[256];
    __shared__ float sgam[16], sbet[16];
    rs[threadIdx.x] = s; rs2[threadIdx.x] = s2;
    if (threadIdx.x < 16) { sgam[threadIdx.x] = gamma[g * 16 + threadIdx.x];
                            sbet[threadIdx.x] = beta [g * 16 + threadIdx.x]; }
    __syncthreads();
    for (int o = 128; o > 0; o >>= 1) {
        if (threadIdx.x < o) { rs[threadIdx.x] += rs[threadIdx.x + o]; rs2[threadIdx.x] += rs2[threadIdx.x + o]; }
        __syncthreads();
    }
    float mean = rs[0] * (1.f / 16384.f);
    float var  = rs2[0] * (1.f / 16384.f) - mean * mean;
    float inv  = rsqrtf(var + 1e-5f);
    for (int pp = 0; pp < 4; pp++) {
        int pos = pp * 256 + threadIdx.x;
        __nv_bfloat16 o16[16];
        #pragma unroll
        for (int c = 0; c < 16; c++)
            o16[c] = __float2bfloat16_rn((xp[c * HW + pos] - mean) * inv * sgam[c] + sbet[c]);
        __nv_bfloat16* dst = g_hT + ((size_t)b * HW + pos) * C_ + g * 16;
        *(uint4*)dst       = *(uint4*)&o16[0];
        *(uint4*)(dst + 8) = *(uint4*)&o16[8];
    }
}

// ---------------- GEMM via mma.sync (tile 128x128, k-chunk 32, double-buffered) ----------------
// smem: A stages @0/@10240, B stages @20480/@30720; row pitch 80B (40 bf16) -> conflict-free ldmatrix
#define GEMM_SMEM 40960

__global__ __launch_bounds__(256) void gemm_kernel(int mode, const float* __restrict__ bias,
                                                   const float* __restrict__ xres,
                                                   float* __restrict__ out) {
    extern __shared__ char smraw[];
    uint32_t sbase = smem_u32(smraw);
    int b = blockIdx.z;
    int n0 = blockIdx.x * 128, m0 = blockIdx.y * 128;
    const __nv_bfloat16 *gA, *gB;
    if (mode == 0) { gA = g_hT + ((size_t)b * HW + m0) * C_;  gB = g_wqkv + (size_t)n0 * C_; }
    else           { gA = g_wproj + (size_t)m0 * C_;          gB = g_attnT + ((size_t)b * HW + n0) * C_; }

    int tid = threadIdx.x, w = tid >> 5, lane = tid & 31;
    int wm = w >> 1, wn = w & 1;

    float acc[2][8][4];
    #pragma unroll
    for (int mt = 0; mt < 2; mt++)
        #pragma unroll
        for (int nt = 0; nt < 8; nt++)
            #pragma unroll
            for (int q = 0; q < 4; q++) acc[mt][nt][q] = 0.f;

    int lrow = tid >> 1, lcc = (tid & 1) * 2;
    const __nv_bfloat16* gArow = gA + (size_t)lrow * C_ + lcc * 8;
    const __nv_bfloat16* gBrow = gB + (size_t)lrow * C_ + lcc * 8;
    uint32_t sA = sbase + lrow * 80 + lcc * 16;
    uint32_t sB = sbase + 20480 + lrow * 80 + lcc * 16;

    CP16(sA, gArow); CP16(sA + 16, gArow + 8);
    CP16(sB, gBrow); CP16(sB + 16, gBrow + 8);
    CP_COMMIT();

    int arow = lane & 15, asel = lane >> 4;
    int bnrow = (lane & 7) + ((lane >> 4) << 3), bcsel = (lane >> 3) & 1;

    for (int kc = 0; kc < 16; kc++) {
        int st = kc & 1;
        if (kc < 15) {
            int nst = st ^ 1;
            const __nv_bfloat16* a2 = gArow + (kc + 1) * 32;
            const __nv_bfloat16* b2 = gBrow + (kc + 1) * 32;
            uint32_t dA = sA + nst * 10240, dB = sB + nst * 10240;
            CP16(dA, a2); CP16(dA + 16, a2 + 8);
            CP16(dB, b2); CP16(dB + 16, b2 + 8);
            CP_COMMIT();
            CP_WAIT(1);
        } else CP_WAIT(0);
        __syncthreads();

        uint32_t Ab = sbase + st * 10240;
        uint32_t Bb = sbase + 20480 + st * 10240;
        #pragma unroll
        for (int j = 0; j < 2; j++) {
            uint32_t af[2][4];
            #pragma unroll
            for (int mt = 0; mt < 2; mt++)
                ldm_x4(af[mt], Ab + (wm * 32 + mt * 16 + arow) * 80 + (j * 2 + asel) * 16);
            #pragma unroll
            for (int p = 0; p < 4; p++) {
                uint32_t bf[4];
                ldm_x4(bf, Bb + (wn * 64 + p * 16 + bnrow) * 80 + (j * 2 + bcsel) * 16);
                #pragma unroll
                for (int mt = 0; mt < 2; mt++) {
                    mma_bf16(acc[mt][2 * p],     af[mt], bf[0], bf[1]);
                    mma_bf16(acc[mt][2 * p + 1], af[mt], bf[2], bf[3]);
                }
            }
        }
        __syncthreads();
    }

    int r0 = m0 + wm * 32 + (lane >> 2);
    if (mode == 0) {
        #pragma unroll
        for (int mt = 0; mt < 2; mt++) {
            int r = r0 + mt * 16;
            #pragma unroll
            for (int nt = 0; nt < 8; nt++) {
                int col = n0 + wn * 64 + nt * 8 + (lane & 3) * 2;
                float b0v = bias[col], b1v = bias[col + 1];
                float sc = ((col % 192) < 64) ? SCALE_F : 1.f;
                *(__nv_bfloat162*)&g_qkvT[((size_t)b * HW + r) * 1536 + col] =
                    __floats2bfloat162_rn((acc[mt][nt][0] + b0v) * sc, (acc[mt][nt][1] + b1v) * sc);
                *(__nv_bfloat162*)&g_qkvT[((size_t)b * HW + r + 8) * 1536 + col] =
                    __floats2bfloat162_rn((acc[mt][nt][2] + b0v) * sc, (acc[mt][nt][3] + b1v) * sc);
            }
        }
    } else {
        #pragma unroll
        for (int mt = 0; mt < 2; mt++) {
            int r = r0 + mt * 16;
            float bi0 = bias[r], bi1 = bias[r + 8];
            #pragma unroll
            for (int nt = 0; nt < 8; nt++) {
                int col = n0 + wn * 64 + nt * 8 + (lane & 3) * 2;
                float2 xa = *(const float2*)(xres + ((size_t)b * C_ + r) * HW + col);
                float2 xb = *(const float2*)(xres + ((size_t)b * C_ + r + 8) * HW + col);
                float2 o0 = { acc[mt][nt][0] + bi0 + xa.x, acc[mt][nt][1] + bi0 + xa.y };
                float2 o1 = { acc[mt][nt][2] + bi1 + xb.x, acc[mt][nt][3] + bi1 + xb.y };
                *(float2*)(out + ((size_t)b * C_ + r) * HW + col)     = o0;
                *(float2*)(out + ((size_t)b * C_ + r + 8) * HW + col) = o1;
            }
        }
    }
}

// ---------------- fused attention (mma.sync flash-style, no-max softmax) ----------------
// smem: Q[128][144B]@0 (18432), K stages @18432+st*9216, V stages @36864+st*9216; total 55296
#define QPITCH 144
#define ATTN_SMEM 55296

__global__ __launch_bounds__(256) void attn_kernel() {
    extern __shared__ char smraw[];
    uint32_t sbase = smem_u32(smraw);
    int bh = blockIdx.y, bb = bh >> 3, head = bh & 7;
    int q0 = blockIdx.x * 128;
    int tid = threadIdx.x, w = tid >> 5, lane = tid & 31;
    const __nv_bfloat16* qkvb = g_qkvT + (size_t)bb * HW * 1536;
    int hb = head * 192;

    // Q tile (q pre-scaled in qkv epilogue)
    {
        int row = tid >> 1, c0 = (tid & 1) * 4;
        const __nv_bfloat16* src = qkvb + (size_t)(q0 + row) * 1536 + hb + c0 * 8;
        uint32_t dst = sbase + row * QPITCH + c0 * 16;
        CP16(dst, src); CP16(dst + 16, src + 8); CP16(dst + 32, src + 16); CP16(dst + 48, src + 24);
    }
    CP_COMMIT();

    int kvrow = tid >> 2, kvc = (tid & 3) * 2;
    const __nv_bfloat16* gK = qkvb + hb + 64;
    const __nv_bfloat16* gV = qkvb + hb + 128;
    // stage 0
    {
        const __nv_bfloat16* ks = gK + (size_t)kvrow * 1536 + kvc * 8;
        const __nv_bfloat16* vs = gV + (size_t)kvrow * 1536 + kvc * 8;
        uint32_t kd = sbase + 18432 + kvrow * QPITCH + kvc * 16;
        uint32_t vd = sbase + 36864 + kvrow * QPITCH + kvc * 16;
        CP16(kd, ks); CP16(kd + 16, ks + 8);
        CP16(vd, vs); CP16(vd + 16, vs + 8);
    }
    CP_COMMIT();
    CP_WAIT(0);
    __syncthreads();

    // Q fragments (register-resident)
    uint32_t qf[4][4];
    {
        int arow = lane & 15, asel = lane >> 4;
        #pragma unroll
        for (int j = 0; j < 4; j++)
            ldm_x4(qf[j], sbase + (w * 16 + arow) * QPITCH + (j * 2 + asel) * 16);
    }

    float oacc[8][4];
    #pragma unroll
    for (int nt = 0; nt < 8; nt++)
        #pragma unroll
        for (int q = 0; q < 4; q++) oacc[nt][q] = 0.f;
    float l0 = 0.f, l1 = 0.f;

    int bnrow = (lane & 7) + ((lane >> 4) << 3), bcsel = (lane >> 3) & 1; // K non-trans
    int vkey  = (lane & 7) + (((lane >> 3) & 1) << 3), vcsel = lane >> 4; // V trans

    for (int kc = 0; kc < 16; kc++) {
        int st = kc & 1;
        if (kc < 15) {
            int nst = st ^ 1;
            const __nv_bfloat16* ks = gK + (size_t)((kc + 1) * 64 + kvrow) * 1536 + kvc * 8;
            const __nv_bfloat16* vs = gV + (size_t)((kc + 1) * 64 + kvrow) * 1536 + kvc * 8;
            uint32_t kd = sbase + 18432 + nst * 9216 + kvrow * QPITCH + kvc * 16;
            uint32_t vd = sbase + 36864 + nst * 9216 + kvrow * QPITCH + kvc * 16;
            CP16(kd, ks); CP16(kd + 16, ks + 8);
            CP16(vd, vs); CP16(vd + 16, vs + 8);
            CP_COMMIT();
            CP_WAIT(1);
        } else CP_WAIT(0);
        __syncthreads();

        uint32_t Kb = sbase + 18432 + st * 9216;
        uint32_t Vb = sbase + 36864 + st * 9216;

        float sacc[8][4];
        #pragma unroll
        for (int nt = 0; nt < 8; nt++)
            #pragma unroll
            for (int q = 0; q < 4; q++) sacc[nt][q] = 0.f;

        #pragma unroll
        for (int j = 0; j < 4; j++) {        // k over head channels
            #pragma unroll
            for (int p = 0; p < 4; p++) {    // key tiles of 16
                uint32_t bf[4];
                ldm_x4(bf, Kb + (p * 16 + bnrow) * QPITCH + (j * 2 + bcsel) * 16);
                mma_bf16(sacc[2 * p],     qf[j], bf[0], bf[1]);
                mma_bf16(sacc[2 * p + 1], qf[j], bf[2], bf[3]);
            }
        }

        // exp + repack S-acc -> P A-fragments (register identity)
        uint32_t pf[4][4];
        #pragma unroll
        for (int j = 0; j < 4; j++) {
            float e00 = __expf(sacc[2 * j][0]),     e01 = __expf(sacc[2 * j][1]);
            float e02 = __expf(sacc[2 * j][2]),     e03 = __expf(sacc[2 * j][3]);
            float e10 = __expf(sacc[2 * j + 1][0]), e11 = __expf(sacc[2 * j + 1][1]);
            float e12 = __expf(sacc[2 * j + 1][2]), e13 = __expf(sacc[2 * j + 1][3]);
            l0 += e00 + e01 + e10 + e11;
            l1 += e02 + e03 + e12 + e13;
            pf[j][0] = pack_bf2(e00, e01);   // (row,   k-lo)
            pf[j][1] = pack_bf2(e02, e03);   // (row+8, k-lo)
            pf[j][2] = pack_bf2(e10, e11);   // (row,   k-hi)
            pf[j][3] = pack_bf2(e12, e13);   // (row+8, k-hi)
        }

        // O += P @ V  (V transposed on the fly via ldmatrix.trans)
        #pragma unroll
        for (int p = 0; p < 4; p++) {        // ch tiles of 16
            #pragma unroll
            for (int j = 0; j < 4; j++) {    // key k16 steps
                uint32_t vf[4];
                ldm_x4t(vf, Vb + (j * 16 + vkey) * QPITCH + (p * 2 + vcsel) * 16);
                mma_bf16(oacc[2 * p],     pf[j], vf[0], vf[1]);
                mma_bf16(oacc[2 * p + 1], pf[j], vf[2], vf[3]);
            }
        }
        __syncthreads();
    }

    l0 += __shfl_xor_sync(0xffffffffu, l0, 1);
    l0 += __shfl_xor_sync(0xffffffffu, l0, 2);
    l1 += __shfl_xor_sync(0xffffffffu, l1, 1);
    l1 += __shfl_xor_sync(0xffffffffu, l1, 2);
    float inv0 = 1.f / l0, inv1 = 1.f / l1;

    int ob = bh & 15, oh = bh >> 4;   // reference's head-major permutation
    int r = q0 + w * 16 + (lane >> 2);
    __nv_bfloat16* d0 = g_attnT + ((size_t)ob * HW + r) * C_ + oh * 64;
    __nv_bfloat16* d1 = g_attnT + ((size_t)ob * HW + r + 8) * C_ + oh * 64;
    #pragma unroll
    for (int nt = 0; nt < 8; nt++) {
        int ch = nt * 8 + (lane & 3) * 2;
        *(__nv_bfloat162*)(d0 + ch) = __floats2bfloat162_rn(oacc[nt][0] * inv0, oacc[nt][1] * inv0);
        *(__nv_bfloat162*)(d1 + ch) = __floats2bfloat162_rn(oacc[nt][2] * inv1, oacc[nt][3] * inv1);
    }
}

// ---------------- launch ----------------
extern "C" void kernel_launch(void* const* d_in, const int* in_sizes, int n_in,
                              void* d_out, int out_size) {
    const float* x      = (const float*)d_in[0];
    const float* gamma  = (const float*)d_in[1];
    const float* beta   = (const float*)d_in[2];
    const float* w_qkv  = (const float*)d_in[3];
    const float* b_qkv  = (const float*)d_in[4];
    const float* w_proj = (const float*)d_in[5];
    const float* b_proj = (const float*)d_in[6];
    float* out = (float*)d_out;

    cudaFuncSetAttribute(attn_kernel, cudaFuncAttributeMaxDynamicSharedMemorySize, ATTN_SMEM);

    conv_kernel<<<(3 * C_ * C_ + 255) / 256, 256>>>(w_qkv, w_proj);
    gn_kernel<<<B_ * 32, 256>>>(x, gamma, beta);
    {
        dim3 grid((3 * C_) / 128, HW / 128, B_);   // 12 x 8 x 16
        gemm_kernel<<<grid, 256, GEMM_SMEM>>>(0, b_qkv, nullptr, nullptr);
    }
    {
        dim3 grid(HW / 128, B_ * 8);               // 8 x 128
        attn_kernel<<<grid, 256, ATTN_SMEM>>>();
    }
    {
        dim3 grid(HW / 128, C_ / 128, B_);         // 8 x 4 x 16
        gemm_kernel<<<grid, 256, GEMM_SMEM>>>(1, b_proj, x, out);
    }
}